// round 14
// baseline (speedup 1.0000x reference)
#include <cuda_runtime.h>
#include <cuda_fp16.h>
#include <cstdint>

#define B_  256
#define T_  1000
#define I_  64
#define H_  128
#define G_  384   // 3*H

typedef unsigned long long u64;

// Scratch for the precomputed input projection x_proj[B][T][3H] (bias folded in).
__device__ float g_xproj[(size_t)B_ * T_ * G_];

// ---- packed fp32x2 helpers (sm_100+) ----------------------------------------
__device__ __forceinline__ u64 fma2(u64 a, u64 b, u64 c) {
    u64 d;
    asm("fma.rn.f32x2 %0, %1, %2, %3;" : "=l"(d) : "l"(a), "l"(b), "l"(c));
    return d;
}
__device__ __forceinline__ float sum2(u64 a) {
    unsigned lo, hi;
    asm("mov.b64 {%0, %1}, %2;" : "=r"(lo), "=r"(hi) : "l"(a));
    return __uint_as_float(lo) + __uint_as_float(hi);
}
__device__ __forceinline__ u64 pack2(float x, float y) {
    u64 r;
    asm("mov.b64 %0, {%1, %2};" : "=l"(r) : "f"(x), "f"(y));
    return r;
}
__device__ __forceinline__ float tanha(float x) {
    float y;
    asm("tanh.approx.f32 %0, %1;" : "=f"(y) : "f"(x));
    return y;
}
__device__ __forceinline__ void cp_async16(uint32_t s, const void* g) {
    asm volatile("cp.async.ca.shared.global [%0], [%1], 16;" :: "r"(s), "l"(g));
}

// ---------------------------------------------------------------------------
// Kernel A: persistent x_proj GEMM. 148 CTAs x 512 threads (R13 layout).
// acc initialized to {bias, 0} so the bias add is free.
// ---------------------------------------------------------------------------
#define XP_NT   ((B_ * T_) / 32)   // 8000 tiles
#define XP_GRID 148

__global__ __launch_bounds__(512) void xproj_kernel(
    const float* __restrict__ input,
    const float* __restrict__ W_ih,
    const float* __restrict__ b_ih)
{
    extern __shared__ __align__(16) char xraw[];
    ulonglong2* Wst = (ulonglong2*)xraw;           // [16 kk2][384 g] = 98304 B
    u64* bufA = (u64*)(xraw + 98304);              // 2 x [32][34] k-pairs

    const int t = threadIdx.x;
    const int tx = t & 127;
    const int ty = t >> 7;            // warp-uniform

    // W_ih -> SMEM transposed: Wst[kk2*384 + g] = W_ih[g][4kk2 .. 4kk2+3].
    {
        const ulonglong2* wu = (const ulonglong2*)W_ih;   // [g][16] chunks
        #pragma unroll
        for (int p = 0; p < 12; ++p) {
            int idx = t + p * 512;
            int kk2 = idx & 15, g = idx >> 4;
            Wst[kk2 * 384 + g] = wu[g * 16 + kk2];
        }
    }
    u64 binit[3];
    #pragma unroll
    for (int jn = 0; jn < 3; ++jn) binit[jn] = pack2(b_ih[tx + jn * 128], 0.f);

    const int pr  = t >> 4;
    const int pc  = t & 15;
    uint32_t dst0 = (uint32_t)__cvta_generic_to_shared(&bufA[pr * 34 + pc * 2]);
    uint32_t dst1 = (uint32_t)__cvta_generic_to_shared(&bufA[1088 + pr * 34 + pc * 2]);

    int tile = blockIdx.x;
    if (tile < XP_NT) {
        cp_async16(dst0, input + ((size_t)tile * 32 + pr) * I_ + pc * 4);
        asm volatile("cp.async.commit_group;");
    }

    int p = 0;
    for (; tile < XP_NT; tile += XP_GRID) {
        asm volatile("cp.async.wait_group 0;");
        __syncthreads();
        if (tile + XP_GRID < XP_NT) {
            cp_async16(p ? dst0 : dst1,
                       input + ((size_t)(tile + XP_GRID) * 32 + pr) * I_ + pc * 4);
            asm volatile("cp.async.commit_group;");
        }

        const u64* A = bufA + p * 1088;
        u64 acc[8][3];
        #pragma unroll
        for (int i = 0; i < 8; ++i)
            #pragma unroll
            for (int jn = 0; jn < 3; ++jn) acc[i][jn] = binit[jn];

        #pragma unroll
        for (int kk2 = 0; kk2 < 16; ++kk2) {
            ulonglong2 a2[8], b2[3];
            #pragma unroll
            for (int i = 0; i < 8; ++i)        // warp-uniform row -> broadcast
                a2[i] = *(const ulonglong2*)&A[(ty * 8 + i) * 34 + 2 * kk2];
            #pragma unroll
            for (int jn = 0; jn < 3; ++jn)     // consecutive lanes, no conflict
                b2[jn] = Wst[kk2 * 384 + tx + jn * 128];
            #pragma unroll
            for (int i = 0; i < 8; ++i)
                #pragma unroll
                for (int jn = 0; jn < 3; ++jn) {
                    acc[i][jn] = fma2(a2[i].x, b2[jn].x, acc[i][jn]);
                    acc[i][jn] = fma2(a2[i].y, b2[jn].y, acc[i][jn]);
                }
        }

        #pragma unroll
        for (int i = 0; i < 8; ++i) {
            float* orow = g_xproj + ((size_t)tile * 32 + ty * 8 + i) * G_;
            #pragma unroll
            for (int jn = 0; jn < 3; ++jn)     // 32 consecutive floats / warp
                orow[tx + jn * 128] = sum2(acc[i][jn]);
        }
        p ^= 1;
    }
}

// ---------------------------------------------------------------------------
// Kernel B: GRU recurrence. R11 structure, but gate-n weights held in SMEM as
// FP16 (4 k-pairs per 16B entry): Wn crossbar traffic halves (512 -> 256 wf
// per SM-step). Converted to fp32 in-loop (__half22float2 + mov.b64); all
// accumulation stays fp32 fma2. Gates r,z remain fp32 in registers.
// ---------------------------------------------------------------------------
__global__ __launch_bounds__(512, 1) void gru_kernel(
    const float* __restrict__ W_hh,
    const float* __restrict__ b_hh,
    float* __restrict__ out)
{
    extern __shared__ __align__(16) char smraw[];
    ulonglong2* Wh  = (ulonglong2*)smraw;            // [16 sid][128 j] = 32768 B (fp16)
    u64*   hint = (u64*)(smraw + 32768);             // [64 k2][2 b]   = 1024 B
    float* part = (float*)(smraw + 33792);           // [3][2][4][128] = 12288 B

    const int t = threadIdx.x;
    const int j = t & 127;
    const int q = t >> 7;                            // k-quarter; batch for t<256
    const int b0 = blockIdx.x * 2;

    const u64* W2u = (const u64*)W_hh;               // W_hh[g][k] as k-pairs

    // Gates r,z quarter-slices -> registers (32 u64 = 64 regs), fp32.
    u64 wreg[32];
    #pragma unroll
    for (int gi = 0; gi < 2; ++gi)
        #pragma unroll
        for (int kk = 0; kk < 16; ++kk)
            wreg[gi * 16 + kk] = W2u[(size_t)(gi * 128 + j) * 64 + q * 16 + kk];

    // Gate-n -> SMEM as fp16: Wh[(qq*4 + m2)*128 + jj] = 16B = 4 k-pairs
    // (k2 = qq*16 + 4*m2 .. +3) of gate-n row jj, each pair as one __half2.
    for (int idx = t; idx < 16 * 128; idx += 512) {
        int jj  = idx & 127;
        int sid = idx >> 7;                          // qq*4 + m2
        int qq  = sid >> 2, m2 = sid & 3;
        const float* src = (const float*)&W2u[(size_t)(2 * 128 + jj) * 64 + qq * 16 + m2 * 4];
        union { __half2 h[4]; ulonglong2 v; } u;
        #pragma unroll
        for (int i = 0; i < 4; ++i)
            u.h[i] = __floats2half2_rn(src[2 * i], src[2 * i + 1]);
        Wh[sid * 128 + jj] = u.v;
    }

    const float bh0 = b_hh[j];
    const float bh1 = b_hh[j + 128];
    const float bh2 = b_hh[j + 256];

    if (t < 256) ((float*)hint)[t] = 0.f;
    float hreg = 0.f;

    const int qb = q & 1;   // clamp for safe pointer math on q>=2 threads
    const float* xp  = g_xproj + (size_t)(b0 + qb) * T_ * G_ + j;  // used t<256
    float*       stp = out     + (size_t)(b0 + qb) * T_ * H_ + j;

    const ulonglong2* hvec = (const ulonglong2*)hint;  // [k-pair] -> {b0, b1}
    const ulonglong2* whp  = Wh + (q * 4) * 128 + j;   // my fp16 gate-n slice
    const int hw = (j >> 1) * 4 + q * 2 + (j & 1);     // float slot of h[b=q][j]
    __syncthreads();

    // Prime the W_n pipeline (step-invariant data).
    ulonglong2 wv = whp[0];

    for (int step = 0; step < T_; ++step) {
        // Prefetch this step's input projections (consumed after the barrier).
        float xr = 0.f, xz = 0.f, xn = 0.f;
        if (t < 256) { xr = xp[0]; xz = xp[128]; xn = xp[256]; }

        u64 a00 = 0, a01 = 0, a10 = 0, a11 = 0, a20 = 0, a21 = 0;
        #pragma unroll
        for (int m2 = 0; m2 < 4; ++m2) {
            // Convert this group's 4 fp16 k-pairs to fp32 packed operands.
            union { ulonglong2 v; __half2 h[4]; } cu;
            cu.v = wv;
            u64 w[4];
            #pragma unroll
            for (int i = 0; i < 4; ++i) {
                float2 f = __half22float2(cu.h[i]);
                w[i] = pack2(f.x, f.y);
            }
            if (m2 < 3) wv = whp[(m2 + 1) * 128];    // prefetch next group
            #pragma unroll
            for (int i = 0; i < 4; ++i) {
                const int kk = m2 * 4 + i;
                ulonglong2 h2 = hvec[q * 16 + kk];   // broadcast LDS.128
                a00 = fma2(wreg[kk],      h2.x, a00);
                a01 = fma2(wreg[kk],      h2.y, a01);
                a10 = fma2(wreg[16 + kk], h2.x, a10);
                a11 = fma2(wreg[16 + kk], h2.y, a11);
                a20 = fma2(w[i],          h2.x, a20);
                a21 = fma2(w[i],          h2.y, a21);
            }
        }

        // Quarter partials -> SMEM, j contiguous (1 wavefront per store).
        part[((0 * 2 + 0) * 4 + q) * 128 + j] = sum2(a00);
        part[((0 * 2 + 1) * 4 + q) * 128 + j] = sum2(a01);
        part[((1 * 2 + 0) * 4 + q) * 128 + j] = sum2(a10);
        part[((1 * 2 + 1) * 4 + q) * 128 + j] = sum2(a11);
        part[((2 * 2 + 0) * 4 + q) * 128 + j] = sum2(a20);
        part[((2 * 2 + 1) * 4 + q) * 128 + j] = sum2(a21);
        __syncthreads();

        // Re-prime W_n pipeline for the NEXT step NOW — overlaps the epilogue.
        wv = whp[0];

        if (t < 256) {                           // b = q
            const float* pr = &part[(0 * 2 + q) * 4 * 128 + j];
            const float* pz = &part[(1 * 2 + q) * 4 * 128 + j];
            const float* pn = &part[(2 * 2 + q) * 4 * 128 + j];
            float r0 = pr[0], r1 = pr[128], r2 = pr[256], r3 = pr[384];
            float z0 = pz[0], z1 = pz[128], z2 = pz[256], z3 = pz[384];
            float n0 = pn[0], n1 = pn[128], n2 = pn[256], n3 = pn[384];
            const float hr = (r0 + r1) + (r2 + r3) + bh0;
            const float hz = (z0 + z1) + (z2 + z3) + bh1;
            const float hn = (n0 + n1) + (n2 + n3) + bh2;

            const float r = 0.5f + 0.5f * tanha(0.5f * (xr + hr));
            const float z = 0.5f + 0.5f * tanha(0.5f * (xz + hz));
            const float n = tanha(xn + r * hn);
            hreg = n + z * (hreg - n);           // (1-z)n + z*h

            ((float*)hint)[hw] = hreg;
            stp[0] = hreg;
        }
        xp  += G_;
        stp += H_;
        __syncthreads();                         // h visible for next step
    }

    if (t < 256)
        out[(size_t)B_ * T_ * H_ + (size_t)(b0 + q) * H_ + j] = hreg;
}

// ---------------------------------------------------------------------------
// Launcher
// ---------------------------------------------------------------------------
extern "C" void kernel_launch(void* const* d_in, const int* in_sizes, int n_in,
                              void* d_out, int out_size)
{
    const float* input = (const float*)d_in[0];   // [B, T, I]
    const float* W_ih  = (const float*)d_in[1];   // [3H, I]
    const float* W_hh  = (const float*)d_in[2];   // [3H, H]
    const float* b_ih  = (const float*)d_in[3];   // [3H]
    const float* b_hh  = (const float*)d_in[4];   // [3H]
    float* out = (float*)d_out;

    const int xp_smem = 98304 + 2 * 1088 * 8;     // 115712 B
    cudaFuncSetAttribute(xproj_kernel, cudaFuncAttributeMaxDynamicSharedMemorySize,
                         xp_smem);
    const int gru_smem = 32768 + 1024 + 12288;    // 46080 B
    cudaFuncSetAttribute(gru_kernel, cudaFuncAttributeMaxDynamicSharedMemorySize,
                         gru_smem);

    xproj_kernel<<<XP_GRID, 512, xp_smem>>>(input, W_ih, b_ih);
    gru_kernel<<<B_ / 2, 512, gru_smem>>>(W_hh, b_hh, out);
}

// round 15
// speedup vs baseline: 1.0660x; 1.0660x over previous
#include <cuda_runtime.h>
#include <cstdint>

#define B_  256
#define T_  1000
#define I_  64
#define H_  128
#define G_  384   // 3*H

typedef unsigned long long u64;

// Scratch for the precomputed input projection x_proj[B][T][3H] (bias folded in).
__device__ float g_xproj[(size_t)B_ * T_ * G_];

// ---- packed fp32x2 helpers (sm_100+) ----------------------------------------
__device__ __forceinline__ u64 fma2(u64 a, u64 b, u64 c) {
    u64 d;
    asm("fma.rn.f32x2 %0, %1, %2, %3;" : "=l"(d) : "l"(a), "l"(b), "l"(c));
    return d;
}
__device__ __forceinline__ float sum2(u64 a) {
    unsigned lo, hi;
    asm("mov.b64 {%0, %1}, %2;" : "=r"(lo), "=r"(hi) : "l"(a));
    return __uint_as_float(lo) + __uint_as_float(hi);
}
__device__ __forceinline__ u64 pack2(float x, float y) {
    u64 r;
    asm("mov.b64 %0, {%1, %2};" : "=l"(r) : "f"(x), "f"(y));
    return r;
}
__device__ __forceinline__ float tanha(float x) {
    float y;
    asm("tanh.approx.f32 %0, %1;" : "=f"(y) : "f"(x));
    return y;
}
__device__ __forceinline__ void cp_async16(uint32_t s, const void* g) {
    asm volatile("cp.async.ca.shared.global [%0], [%1], 16;" :: "r"(s), "l"(g));
}

// ---------------------------------------------------------------------------
// Kernel A: persistent x_proj GEMM. 148 CTAs x 512 threads.
// R13 layout (transposed Wst, coalesced stores, broadcast a-loads) plus a
// 1-deep software pipeline on the per-kk2 operand loads: the next iteration's
// 11 LDS are issued before this iteration's 48 fma2, hiding the ~29-cyc LDS
// latency that kept the kernel at 64% of its FMA floor.
// ---------------------------------------------------------------------------
#define XP_NT   ((B_ * T_) / 32)   // 8000 tiles
#define XP_GRID 148

__global__ __launch_bounds__(512) void xproj_kernel(
    const float* __restrict__ input,
    const float* __restrict__ W_ih,
    const float* __restrict__ b_ih)
{
    extern __shared__ __align__(16) char xraw[];
    ulonglong2* Wst = (ulonglong2*)xraw;           // [16 kk2][384 g] = 98304 B
    u64* bufA = (u64*)(xraw + 98304);              // 2 x [32][34] k-pairs

    const int t = threadIdx.x;
    const int tx = t & 127;
    const int ty = t >> 7;            // warp-uniform

    // W_ih -> SMEM transposed: Wst[kk2*384 + g] = W_ih[g][4kk2 .. 4kk2+3].
    {
        const ulonglong2* wu = (const ulonglong2*)W_ih;   // [g][16] chunks
        #pragma unroll
        for (int p = 0; p < 12; ++p) {
            int idx = t + p * 512;
            int kk2 = idx & 15, g = idx >> 4;
            Wst[kk2 * 384 + g] = wu[g * 16 + kk2];
        }
    }
    u64 binit[3];
    #pragma unroll
    for (int jn = 0; jn < 3; ++jn) binit[jn] = pack2(b_ih[tx + jn * 128], 0.f);

    const int pr  = t >> 4;
    const int pc  = t & 15;
    uint32_t dst0 = (uint32_t)__cvta_generic_to_shared(&bufA[pr * 34 + pc * 2]);
    uint32_t dst1 = (uint32_t)__cvta_generic_to_shared(&bufA[1088 + pr * 34 + pc * 2]);

    int tile = blockIdx.x;
    if (tile < XP_NT) {
        cp_async16(dst0, input + ((size_t)tile * 32 + pr) * I_ + pc * 4);
        asm volatile("cp.async.commit_group;");
    }

    int p = 0;
    for (; tile < XP_NT; tile += XP_GRID) {
        asm volatile("cp.async.wait_group 0;");
        __syncthreads();
        if (tile + XP_GRID < XP_NT) {
            cp_async16(p ? dst0 : dst1,
                       input + ((size_t)(tile + XP_GRID) * 32 + pr) * I_ + pc * 4);
            asm volatile("cp.async.commit_group;");
        }

        const u64* A = bufA + p * 1088;
        u64 acc[8][3];
        #pragma unroll
        for (int i = 0; i < 8; ++i)
            #pragma unroll
            for (int jn = 0; jn < 3; ++jn) acc[i][jn] = binit[jn];

        // 1-deep software-pipelined operand loads.
        ulonglong2 a2[8], b2[3];
        #pragma unroll
        for (int i = 0; i < 8; ++i)
            a2[i] = *(const ulonglong2*)&A[(ty * 8 + i) * 34];
        #pragma unroll
        for (int jn = 0; jn < 3; ++jn)
            b2[jn] = Wst[tx + jn * 128];

        #pragma unroll
        for (int kk2 = 0; kk2 < 16; ++kk2) {
            ulonglong2 an[8], bn[3];
            if (kk2 < 15) {
                #pragma unroll
                for (int i = 0; i < 8; ++i)
                    an[i] = *(const ulonglong2*)&A[(ty * 8 + i) * 34 + 2 * (kk2 + 1)];
                #pragma unroll
                for (int jn = 0; jn < 3; ++jn)
                    bn[jn] = Wst[(kk2 + 1) * 384 + tx + jn * 128];
            }
            #pragma unroll
            for (int i = 0; i < 8; ++i)
                #pragma unroll
                for (int jn = 0; jn < 3; ++jn) {
                    acc[i][jn] = fma2(a2[i].x, b2[jn].x, acc[i][jn]);
                    acc[i][jn] = fma2(a2[i].y, b2[jn].y, acc[i][jn]);
                }
            if (kk2 < 15) {
                #pragma unroll
                for (int i = 0; i < 8; ++i) a2[i] = an[i];
                #pragma unroll
                for (int jn = 0; jn < 3; ++jn) b2[jn] = bn[jn];
            }
        }

        #pragma unroll
        for (int i = 0; i < 8; ++i) {
            float* orow = g_xproj + ((size_t)tile * 32 + ty * 8 + i) * G_;
            #pragma unroll
            for (int jn = 0; jn < 3; ++jn)     // 32 consecutive floats / warp
                orow[tx + jn * 128] = sum2(acc[i][jn]);
        }
        p ^= 1;
    }
}

// ---------------------------------------------------------------------------
// Kernel B: GRU recurrence — FROZEN R11 configuration (measured 810-812us 3x).
// ---------------------------------------------------------------------------
__global__ __launch_bounds__(512, 1) void gru_kernel(
    const float* __restrict__ W_hh,
    const float* __restrict__ b_hh,
    float* __restrict__ out)
{
    extern __shared__ __align__(16) char smraw[];
    ulonglong2* Wnp = (ulonglong2*)smraw;            // [32 sid][128 j] = 65536 B
    u64*   hint = (u64*)(smraw + 65536);             // [64 k2][2 b]   = 1024 B
    float* part = (float*)(smraw + 66560);           // [3][2][4][128] = 12288 B

    const int t = threadIdx.x;
    const int j = t & 127;
    const int q = t >> 7;                            // k-quarter; batch for t<256
    const int b0 = blockIdx.x * 2;

    const u64* W2u = (const u64*)W_hh;               // W_hh[g][k] as k-pairs

    // Gates r,z quarter-slices -> registers (32 u64 = 64 regs).
    u64 wreg[32];
    #pragma unroll
    for (int gi = 0; gi < 2; ++gi)
        #pragma unroll
        for (int kk = 0; kk < 16; ++kk)
            wreg[gi * 16 + kk] = W2u[(size_t)(gi * 128 + j) * 64 + q * 16 + kk];

    // Gate-n -> SMEM as paired k2: Wnp[qq*8 + m][g] = {k2=qq*16+2m, +2m+1}.
    for (int idx = t; idx < 32 * 128; idx += 512) {
        int g   = idx & 127;
        int sid = idx >> 7;                          // qq*8 + m
        int qq  = sid >> 3, m = sid & 7;
        const u64* src = &W2u[(size_t)(2 * 128 + g) * 64 + qq * 16 + 2 * m];
        ulonglong2 v; v.x = src[0]; v.y = src[1];
        Wnp[sid * 128 + g] = v;
    }

    const float bh0 = b_hh[j];
    const float bh1 = b_hh[j + 128];
    const float bh2 = b_hh[j + 256];

    if (t < 256) ((float*)hint)[t] = 0.f;
    float hreg = 0.f;

    const int qb = q & 1;   // clamp for safe pointer math on q>=2 threads
    const float* xp  = g_xproj + (size_t)(b0 + qb) * T_ * G_ + j;  // used t<256
    float*       stp = out     + (size_t)(b0 + qb) * T_ * H_ + j;

    const ulonglong2* hvec = (const ulonglong2*)hint;  // [k-pair] -> {b0, b1}
    const ulonglong2* wnp  = Wnp + (q * 8) * 128 + j;  // my gate-n smem slice
    const int hw = (j >> 1) * 4 + q * 2 + (j & 1);     // float slot of h[b=q][j]
    __syncthreads();

    // Prime the 2-deep W_n pipeline (step-invariant data).
    ulonglong2 w2a = wnp[0];
    ulonglong2 w2b = wnp[128];

    for (int step = 0; step < T_; ++step) {
        // Prefetch this step's input projections (consumed after the barrier).
        float xr = 0.f, xz = 0.f, xn = 0.f;
        if (t < 256) { xr = xp[0]; xz = xp[128]; xn = xp[256]; }

        u64 a00 = 0, a01 = 0, a10 = 0, a11 = 0, a20 = 0, a21 = 0;
        #pragma unroll
        for (int m = 0; m < 8; ++m) {
            ulonglong2 h2a = hvec[q * 16 + 2 * m];       // broadcast
            ulonglong2 h2b = hvec[q * 16 + 2 * m + 1];   // broadcast
            ulonglong2 w2c = w2a;
            w2a = w2b;
            if (m < 6) w2b = wnp[(m + 2) * 128];         // distance-2 prefetch
            a00 = fma2(wreg[2 * m],          h2a.x, a00);
            a01 = fma2(wreg[2 * m],          h2a.y, a01);
            a10 = fma2(wreg[16 + 2 * m],     h2a.x, a10);
            a11 = fma2(wreg[16 + 2 * m],     h2a.y, a11);
            a20 = fma2(w2c.x,                h2a.x, a20);
            a21 = fma2(w2c.x,                h2a.y, a21);
            a00 = fma2(wreg[2 * m + 1],      h2b.x, a00);
            a01 = fma2(wreg[2 * m + 1],      h2b.y, a01);
            a10 = fma2(wreg[16 + 2 * m + 1], h2b.x, a10);
            a11 = fma2(wreg[16 + 2 * m + 1], h2b.y, a11);
            a20 = fma2(w2c.y,                h2b.x, a20);
            a21 = fma2(w2c.y,                h2b.y, a21);
        }

        // Quarter partials -> SMEM, j contiguous (1 wavefront per store).
        part[((0 * 2 + 0) * 4 + q) * 128 + j] = sum2(a00);
        part[((0 * 2 + 1) * 4 + q) * 128 + j] = sum2(a01);
        part[((1 * 2 + 0) * 4 + q) * 128 + j] = sum2(a10);
        part[((1 * 2 + 1) * 4 + q) * 128 + j] = sum2(a11);
        part[((2 * 2 + 0) * 4 + q) * 128 + j] = sum2(a20);
        part[((2 * 2 + 1) * 4 + q) * 128 + j] = sum2(a21);
        __syncthreads();

        // Re-prime W_n pipeline for the NEXT step NOW — overlaps the epilogue.
        w2a = wnp[0];
        w2b = wnp[128];

        if (t < 256) {                           // b = q
            const float* pr = &part[(0 * 2 + q) * 4 * 128 + j];
            const float* pz = &part[(1 * 2 + q) * 4 * 128 + j];
            const float* pn = &part[(2 * 2 + q) * 4 * 128 + j];
            float r0 = pr[0], r1 = pr[128], r2 = pr[256], r3 = pr[384];
            float z0 = pz[0], z1 = pz[128], z2 = pz[256], z3 = pz[384];
            float n0 = pn[0], n1 = pn[128], n2 = pn[256], n3 = pn[384];
            const float hr = (r0 + r1) + (r2 + r3) + bh0;
            const float hz = (z0 + z1) + (z2 + z3) + bh1;
            const float hn = (n0 + n1) + (n2 + n3) + bh2;

            const float r = 0.5f + 0.5f * tanha(0.5f * (xr + hr));
            const float z = 0.5f + 0.5f * tanha(0.5f * (xz + hz));
            const float n = tanha(xn + r * hn);
            hreg = n + z * (hreg - n);           // (1-z)n + z*h

            ((float*)hint)[hw] = hreg;
            stp[0] = hreg;
        }
        xp  += G_;
        stp += H_;
        __syncthreads();                         // h visible for next step
    }

    if (t < 256)
        out[(size_t)B_ * T_ * H_ + (size_t)(b0 + q) * H_ + j] = hreg;
}

// ---------------------------------------------------------------------------
// Launcher
// ---------------------------------------------------------------------------
extern "C" void kernel_launch(void* const* d_in, const int* in_sizes, int n_in,
                              void* d_out, int out_size)
{
    const float* input = (const float*)d_in[0];   // [B, T, I]
    const float* W_ih  = (const float*)d_in[1];   // [3H, I]
    const float* W_hh  = (const float*)d_in[2];   // [3H, H]
    const float* b_ih  = (const float*)d_in[3];   // [3H]
    const float* b_hh  = (const float*)d_in[4];   // [3H]
    float* out = (float*)d_out;

    const int xp_smem = 98304 + 2 * 1088 * 8;     // 115712 B
    cudaFuncSetAttribute(xproj_kernel, cudaFuncAttributeMaxDynamicSharedMemorySize,
                         xp_smem);
    const int gru_smem = 65536 + 1024 + 12288;    // 78848 B
    cudaFuncSetAttribute(gru_kernel, cudaFuncAttributeMaxDynamicSharedMemorySize,
                         gru_smem);

    xproj_kernel<<<XP_GRID, 512, xp_smem>>>(input, W_ih, b_ih);
    gru_kernel<<<B_ / 2, 512, gru_smem>>>(W_hh, b_hh, out);
}